// round 9
// baseline (speedup 1.0000x reference)
#include <cuda_runtime.h>
#include <cstdint>

// IndexAddInplace as a GATHER: out[j] = x[j] + sum_{i: idx[i]==j} src[i]
// x: [N_DST=100000, D=512] f32, idx: [N_SRC=200000] int64/int32 (detected),
// src: [N_SRC, D] f32.
//
// build : K inline slots per dst row (atomicAdd counter) + linked-list spill
//         (i+1 encoded, 0 = end => zero-init IS the empty state).
// gather: one warp per TWO rows (4 float4/lane/row) — 8 independent x-loads
//         plus up to 8*K independent src LDG.128s per warp. Doubling per-warp
//         bytes-in-flight is the lever that moved DRAM% in R5->R6; occupancy
//         drop is affordable (memory-latency-bound, not issue-bound).
//         Self-cleans cnt/head behind __syncwarp() (warp-private state).
// Traffic floor: 205MB x-read + 410MB src-read + 205MB out-write (+~4MB index).

#define MAX_DST 100000
#define MAX_SRC 200000
#define K_SLOTS 6
#define DETECT_WORDS 512    // odd-word sample for dtype detection

__device__ int g_cnt[MAX_DST];               // zero-init = empty
__device__ int g_slot[MAX_DST * K_SLOTS];
__device__ int g_head[MAX_DST];              // stores i+1; 0 = end (zero-init OK)
__device__ int g_next[MAX_SRC];              // stores i+1 links

// ---- 1. build inverted index (exact grid: one element per thread) ----
// Per-block dtype detect: int64 idx with values < 2^31 has ALL odd 32-bit
// words == 0 (LE); int32 idx has random dst indices there (P(all 0) ~ 0).
__global__ void build_kernel(const void* __restrict__ idx_raw, int n_src) {
    const int* idx32 = (const int*)idx_raw;
    int local = 0;
    #pragma unroll
    for (int k = 0; k < DETECT_WORDS / 256; k++) {
        int w = threadIdx.x + k * 256;
        if (2 * w + 1 < n_src) local |= idx32[2 * w + 1];
    }
    const int is64 = !__syncthreads_or(local != 0);

    int i = blockIdx.x * blockDim.x + threadIdx.x;
    if (i >= n_src) return;

    int d;
    if (is64) d = (int)((const long long*)idx_raw)[i];
    else      d = idx32[i];

    int pos = atomicAdd(&g_cnt[d], 1);
    if (pos < K_SLOTS) g_slot[d * K_SLOTS + pos] = i;
    else               g_next[i] = atomicExch(&g_head[d], i + 1);
}

// ---- helper: accumulate one row's slot sources into acc[4] ----
__device__ __forceinline__ void accum_row(const float4* __restrict__ src,
                                          float4 acc[4], const int* ids, int m,
                                          int dv, int lane) {
    #pragma unroll
    for (int k = 0; k < K_SLOTS; k++) {
        if (k < m) {
            const size_t sbase = (size_t)ids[k] * dv + lane;
            #pragma unroll
            for (int q = 0; q < 4; q++) {
                float4 v = __ldcs(&src[sbase + q * 32]);
                acc[q].x += v.x; acc[q].y += v.y;
                acc[q].z += v.z; acc[q].w += v.w;
            }
        }
    }
}

__device__ __forceinline__ void accum_spill(const float4* __restrict__ src,
                                            float4 acc[4], int j,
                                            int dv, int lane) {
    for (int v1 = __ldg(&g_head[j]); v1 != 0; v1 = __ldg(&g_next[v1 - 1])) {
        const size_t sbase = (size_t)(v1 - 1) * dv + lane;
        #pragma unroll
        for (int q = 0; q < 4; q++) {
            float4 v = __ldcs(&src[sbase + q * 32]);
            acc[q].x += v.x; acc[q].y += v.y;
            acc[q].z += v.z; acc[q].w += v.w;
        }
    }
}

// ---- 2. gather: one warp per TWO consecutive rows ----
__global__ void __launch_bounds__(128)
gather_kernel(const float4* __restrict__ x,
              const float4* __restrict__ src,
              float4* __restrict__ out,
              int dv, int n_dst) {
    const int warp_id = (blockIdx.x * blockDim.x + threadIdx.x) >> 5;
    const int lane = threadIdx.x & 31;

    const int j0 = warp_id * 2;
    if (j0 >= n_dst) return;
    const bool has1 = (j0 + 1) < n_dst;
    const int j1 = has1 ? j0 + 1 : j0;

    // Warp-uniform counts (L2-resident), issued back-to-back.
    const int n0 = __ldg(&g_cnt[j0]);
    const int n1 = has1 ? __ldg(&g_cnt[j1]) : 0;
    const int m0 = n0 < K_SLOTS ? n0 : K_SLOTS;
    const int m1 = n1 < K_SLOTS ? n1 : K_SLOTS;

    const size_t rbase0 = (size_t)j0 * dv + lane;    // dv = 128
    const size_t rbase1 = (size_t)j1 * dv + lane;

    // 8 independent streaming x-loads (front-batched by ptxas).
    float4 acc0[4], acc1[4];
    #pragma unroll
    for (int q = 0; q < 4; q++) acc0[q] = __ldcs(&x[rbase0 + q * 32]);
    #pragma unroll
    for (int q = 0; q < 4; q++) acc1[q] = __ldcs(&x[rbase1 + q * 32]);

    // Slot indices for both rows (warp-uniform, L2).
    int ids0[K_SLOTS], ids1[K_SLOTS];
    #pragma unroll
    for (int k = 0; k < K_SLOTS; k++) {
        if (k < m0) ids0[k] = __ldg(&g_slot[j0 * K_SLOTS + k]);
        if (k < m1) ids1[k] = __ldg(&g_slot[j1 * K_SLOTS + k]);
    }

    accum_row(src, acc0, ids0, m0, dv, lane);
    accum_row(src, acc1, ids1, m1, dv, lane);

    // Rare spill (>K sources, ~0.45% of rows).
    if (n0 > K_SLOTS) accum_spill(src, acc0, j0, dv, lane);
    if (has1 && n1 > K_SLOTS) accum_spill(src, acc1, j1, dv, lane);

    #pragma unroll
    for (int q = 0; q < 4; q++) __stcs(&out[rbase0 + q * 32], acc0[q]);
    if (has1) {
        #pragma unroll
        for (int q = 0; q < 4; q++) __stcs(&out[rbase1 + q * 32], acc1[q]);
    }

    // Whole warp has consumed both rows' state before lane 0 resets them.
    __syncwarp();
    if (lane == 0) {
        g_cnt[j0] = 0;
        if (n0 > K_SLOTS) g_head[j0] = 0;
        if (has1) {
            g_cnt[j1] = 0;
            if (n1 > K_SLOTS) g_head[j1] = 0;
        }
    }
}

extern "C" void kernel_launch(void* const* d_in, const int* in_sizes, int n_in,
                              void* d_out, int out_size) {
    // Inputs: x [N_DST*D] f32, idx [N_SRC], src [N_SRC*D] f32
    const float* x   = (const float*)d_in[0];
    const void*  idx = (const void*)d_in[1];
    const float* src = (const float*)d_in[2];
    float* out = (float*)d_out;

    const int n_src = in_sizes[1];             // 200000
    const int d     = in_sizes[2] / n_src;     // 512
    const int n_dst = out_size / d;            // 100000
    const int dv    = d / 4;                   // 128 float4/row

    build_kernel<<<(n_src + 255) / 256, 256>>>(idx, n_src);

    const int rows_per_block = 4 * 2;          // 4 warps * 2 rows
    gather_kernel<<<(n_dst + rows_per_block - 1) / rows_per_block, 128>>>(
        (const float4*)x, (const float4*)src, (float4*)out, dv, n_dst);
}

// round 10
// speedup vs baseline: 1.1201x; 1.1201x over previous
#include <cuda_runtime.h>
#include <cstdint>

// IndexAddInplace as a GATHER: out[j] = x[j] + sum_{i: idx[i]==j} src[i]
// x: [N_DST=100000, D=512] f32, idx: [N_SRC=200000] int64/int32 (detected),
// src: [N_SRC, D] f32.
//
// build : K inline slots per dst row (atomicAdd counter) + linked-list spill
//         (i+1 encoded, 0 = end => zero-init IS the empty state).
// gather: one WARP per row (4 float4/lane) — the proven occupancy x MLP
//         optimum (R5/R6/R9 sweep). This round: 256-thr blocks (half the
//         scheduling events), L2::256B prefetch hints on streaming loads,
//         index reads hoisted ahead of x loads. Self-cleans cnt/head behind
//         __syncwarp() (warp-private state).
// Traffic floor: 205MB x-read + 410MB src-read + 205MB out-write (+~4MB index).

#define MAX_DST 100000
#define MAX_SRC 200000
#define K_SLOTS 6
#define DETECT_WORDS 512    // odd-word sample for dtype detection

__device__ int g_cnt[MAX_DST];               // zero-init = empty
__device__ int g_slot[MAX_DST * K_SLOTS];
__device__ int g_head[MAX_DST];              // stores i+1; 0 = end (zero-init OK)
__device__ int g_next[MAX_SRC];              // stores i+1 links

// Streaming 128-bit load with L2 256B prefetch hint (evict-first policy).
__device__ __forceinline__ float4 ldcs_pf(const float4* p) {
    float4 v;
    asm volatile("ld.global.cs.L2::256B.v4.f32 {%0,%1,%2,%3}, [%4];"
                 : "=f"(v.x), "=f"(v.y), "=f"(v.z), "=f"(v.w)
                 : "l"(p));
    return v;
}

// ---- 1. build inverted index (exact grid: one element per thread) ----
// Per-block dtype detect: int64 idx with values < 2^31 has ALL odd 32-bit
// words == 0 (LE); int32 idx has random dst indices there (P(all 0) ~ 0).
__global__ void build_kernel(const void* __restrict__ idx_raw, int n_src) {
    const int* idx32 = (const int*)idx_raw;
    int local = 0;
    #pragma unroll
    for (int k = 0; k < DETECT_WORDS / 256; k++) {
        int w = threadIdx.x + k * 256;
        if (2 * w + 1 < n_src) local |= idx32[2 * w + 1];
    }
    const int is64 = !__syncthreads_or(local != 0);

    int i = blockIdx.x * blockDim.x + threadIdx.x;
    if (i >= n_src) return;

    int d;
    if (is64) d = (int)((const long long*)idx_raw)[i];
    else      d = idx32[i];

    int pos = atomicAdd(&g_cnt[d], 1);
    if (pos < K_SLOTS) g_slot[d * K_SLOTS + pos] = i;
    else               g_next[i] = atomicExch(&g_head[d], i + 1);
}

// ---- 2. gather: one WARP per row; lane handles cols c, c+32, c+64, c+96 ----
__global__ void __launch_bounds__(256)
gather_kernel(const float4* __restrict__ x,
              const float4* __restrict__ src,
              float4* __restrict__ out,
              int dv, int n_dst) {
    const int warp_id = (blockIdx.x * blockDim.x + threadIdx.x) >> 5;
    if (warp_id >= n_dst) return;
    const int j = warp_id;
    const int lane = threadIdx.x & 31;

    // Index state first: src addresses resolve as early as possible.
    const int n = __ldg(&g_cnt[j]);              // warp-uniform, L2-resident
    const int m = n < K_SLOTS ? n : K_SLOTS;

    int ids[K_SLOTS];
    #pragma unroll
    for (int k = 0; k < K_SLOTS; k++)
        if (k < m) ids[k] = __ldg(&g_slot[j * K_SLOTS + k]);

    const size_t rbase = (size_t)j * dv + lane;  // dv = 128, 4 chunks of 32

    float4 acc[4];
    #pragma unroll
    for (int q = 0; q < 4; q++)
        acc[q] = ldcs_pf(&x[rbase + q * 32]);    // independent streaming loads

    #pragma unroll
    for (int k = 0; k < K_SLOTS; k++) {
        if (k < m) {
            const size_t sbase = (size_t)ids[k] * dv + lane;
            #pragma unroll
            for (int q = 0; q < 4; q++) {
                float4 v = ldcs_pf(&src[sbase + q * 32]);
                acc[q].x += v.x; acc[q].y += v.y;
                acc[q].z += v.z; acc[q].w += v.w;
            }
        }
    }

    // Rare spill (>K sources, ~0.45% of rows): walk the i+1-encoded chain.
    if (n > K_SLOTS) {
        for (int v1 = __ldg(&g_head[j]); v1 != 0; v1 = __ldg(&g_next[v1 - 1])) {
            const size_t sbase = (size_t)(v1 - 1) * dv + lane;
            #pragma unroll
            for (int q = 0; q < 4; q++) {
                float4 v = ldcs_pf(&src[sbase + q * 32]);
                acc[q].x += v.x; acc[q].y += v.y;
                acc[q].z += v.z; acc[q].w += v.w;
            }
        }
    }

    #pragma unroll
    for (int q = 0; q < 4; q++)
        __stcs(&out[rbase + q * 32], acc[q]);

    // Whole warp has consumed this row's state before lane 0 resets it.
    __syncwarp();
    if (lane == 0) {
        g_cnt[j] = 0;
        if (n > K_SLOTS) g_head[j] = 0;
    }
}

extern "C" void kernel_launch(void* const* d_in, const int* in_sizes, int n_in,
                              void* d_out, int out_size) {
    // Inputs: x [N_DST*D] f32, idx [N_SRC], src [N_SRC*D] f32
    const float* x   = (const float*)d_in[0];
    const void*  idx = (const void*)d_in[1];
    const float* src = (const float*)d_in[2];
    float* out = (float*)d_out;

    const int n_src = in_sizes[1];             // 200000
    const int d     = in_sizes[2] / n_src;     // 512
    const int n_dst = out_size / d;            // 100000
    const int dv    = d / 4;                   // 128 float4/row

    build_kernel<<<(n_src + 255) / 256, 256>>>(idx, n_src);

    const int rows_per_block = 256 / 32;       // 8 warps = 8 rows
    gather_kernel<<<(n_dst + rows_per_block - 1) / rows_per_block, 256>>>(
        (const float4*)x, (const float4*)src, (float4*)out, dv, n_dst);
}

// round 11
// speedup vs baseline: 1.1356x; 1.0138x over previous
#include <cuda_runtime.h>
#include <cstdint>

// IndexAddInplace as a GATHER: out[j] = x[j] + sum_{i: idx[i]==j} src[i]
// x: [N_DST=100000, D=512] f32, idx: [N_SRC=200000] int64/int32 (detected),
// src: [N_SRC, D] f32.
//
// build : PACKED per-row metadata: meta[j] = {cnt, slot0..slot6} (32B).
//         atomicAdd on word 0; slots 0..6 inline; >7 sources spill to an
//         i+1-encoded linked list (0 = end => zero-init is the empty state).
// gather: one WARP per row (proven occupancy x MLP optimum). Row metadata is
//         read as TWO UNCONDITIONAL int4 loads -> cnt and all slot ids arrive
//         in ONE L2 round trip (previous layout serialized cnt -> slots,
//         costing an extra ~250cyc on every row's critical path). Then 4
//         independent x LDG.128s + 4*m src LDG.128s. Self-cleans cnt behind
//         __syncwarp().
// Traffic floor: 205MB x-read + 410MB src-read + 205MB out-write (+~5MB index).

#define MAX_DST 100000
#define MAX_SRC 200000
#define K_SLOTS 7            // slots per packed 32B record (word 0 = cnt)
#define DETECT_WORDS 512     // odd-word sample for dtype detection

__device__ int4 g_meta[MAX_DST * 2];         // zero-init => cnt = 0 (empty)
__device__ int  g_head[MAX_DST];             // stores i+1; 0 = end (zero-init OK)
__device__ int  g_next[MAX_SRC];             // stores i+1 links

// Streaming 128-bit load with L2 256B prefetch hint (evict-first policy).
__device__ __forceinline__ float4 ldcs_pf(const float4* p) {
    float4 v;
    asm volatile("ld.global.cs.L2::256B.v4.f32 {%0,%1,%2,%3}, [%4];"
                 : "=f"(v.x), "=f"(v.y), "=f"(v.z), "=f"(v.w)
                 : "l"(p));
    return v;
}

// ---- 1. build inverted index (exact grid: one element per thread) ----
// Per-block dtype detect: int64 idx with values < 2^31 has ALL odd 32-bit
// words == 0 (LE); int32 idx has random dst indices there (P(all 0) ~ 0).
__global__ void build_kernel(const void* __restrict__ idx_raw, int n_src) {
    const int* idx32 = (const int*)idx_raw;
    int local = 0;
    #pragma unroll
    for (int k = 0; k < DETECT_WORDS / 256; k++) {
        int w = threadIdx.x + k * 256;
        if (2 * w + 1 < n_src) local |= idx32[2 * w + 1];
    }
    const int is64 = !__syncthreads_or(local != 0);

    int i = blockIdx.x * blockDim.x + threadIdx.x;
    if (i >= n_src) return;

    int d;
    if (is64) d = (int)((const long long*)idx_raw)[i];
    else      d = idx32[i];

    int* rec = (int*)&g_meta[d * 2];         // {cnt, slot0..slot6}
    int pos = atomicAdd(rec, 1);
    if (pos < K_SLOTS) rec[1 + pos] = i;
    else               g_next[i] = atomicExch(&g_head[d], i + 1);
}

// ---- 2. gather: one WARP per row; lane handles cols c, c+32, c+64, c+96 ----
__global__ void __launch_bounds__(256)
gather_kernel(const float4* __restrict__ x,
              const float4* __restrict__ src,
              float4* __restrict__ out,
              int dv, int n_dst) {
    const int warp_id = (blockIdx.x * blockDim.x + threadIdx.x) >> 5;
    if (warp_id >= n_dst) return;
    const int j = warp_id;
    const int lane = threadIdx.x & 31;

    // Whole row record in two unconditional 16B loads — one L2 round trip,
    // no cnt->slot dependency, no predication.
    const int4 a = __ldg(&g_meta[j * 2]);
    const int4 b = __ldg(&g_meta[j * 2 + 1]);
    const int n = a.x;
    const int m = n < K_SLOTS ? n : K_SLOTS;
    const int ids[K_SLOTS] = { a.y, a.z, a.w, b.x, b.y, b.z, b.w };

    const size_t rbase = (size_t)j * dv + lane;  // dv = 128, 4 chunks of 32

    float4 acc[4];
    #pragma unroll
    for (int q = 0; q < 4; q++)
        acc[q] = ldcs_pf(&x[rbase + q * 32]);    // independent streaming loads

    #pragma unroll
    for (int k = 0; k < K_SLOTS; k++) {
        if (k < m) {
            const size_t sbase = (size_t)ids[k] * dv + lane;
            #pragma unroll
            for (int q = 0; q < 4; q++) {
                float4 v = ldcs_pf(&src[sbase + q * 32]);
                acc[q].x += v.x; acc[q].y += v.y;
                acc[q].z += v.z; acc[q].w += v.w;
            }
        }
    }

    // Rare spill (>7 sources, ~0.1% of rows): walk the i+1-encoded chain.
    if (n > K_SLOTS) {
        for (int v1 = __ldg(&g_head[j]); v1 != 0; v1 = __ldg(&g_next[v1 - 1])) {
            const size_t sbase = (size_t)(v1 - 1) * dv + lane;
            #pragma unroll
            for (int q = 0; q < 4; q++) {
                float4 v = ldcs_pf(&src[sbase + q * 32]);
                acc[q].x += v.x; acc[q].y += v.y;
                acc[q].z += v.z; acc[q].w += v.w;
            }
        }
    }

    #pragma unroll
    for (int q = 0; q < 4; q++)
        __stcs(&out[rbase + q * 32], acc[q]);

    // Whole warp has consumed this row's state before lane 0 resets it.
    __syncwarp();
    if (lane == 0) {
        ((int*)&g_meta[j * 2])[0] = 0;           // cnt = 0 (slots gated by cnt)
        if (n > K_SLOTS) g_head[j] = 0;
    }
}

extern "C" void kernel_launch(void* const* d_in, const int* in_sizes, int n_in,
                              void* d_out, int out_size) {
    // Inputs: x [N_DST*D] f32, idx [N_SRC], src [N_SRC*D] f32
    const float* x   = (const float*)d_in[0];
    const void*  idx = (const void*)d_in[1];
    const float* src = (const float*)d_in[2];
    float* out = (float*)d_out;

    const int n_src = in_sizes[1];             // 200000
    const int d     = in_sizes[2] / n_src;     // 512
    const int n_dst = out_size / d;            // 100000
    const int dv    = d / 4;                   // 128 float4/row

    build_kernel<<<(n_src + 255) / 256, 256>>>(idx, n_src);

    const int rows_per_block = 256 / 32;       // 8 warps = 8 rows
    gather_kernel<<<(n_dst + rows_per_block - 1) / rows_per_block, 256>>>(
        (const float4*)x, (const float4*)src, (float4*)out, dv, n_dst);
}